// round 2
// baseline (speedup 1.0000x reference)
#include <cuda_runtime.h>

#define B_      32
#define DIM_    256
#define N_      512
#define NHEADS  8
#define KDIM    16
#define NH_KD   128
#define DH_     512
#define HQKV    768
#define VDIM    64

// Scratch (device globals: no allocation allowed)
__device__ float g_qkv[(size_t)B_ * HQKV * N_];   // [b][768][512]
__device__ float g_q  [(size_t)B_ * NH_KD * N_];  // dw-conv output
__device__ float g_att[(size_t)B_ * DH_ * N_];    // attention output (pre-relu)

// ---------------------------------------------------------------------------
// Generic tiled fp32 GEMM with per-row scale/bias epilogue (the "_cbn" op).
// C[b] = A[M,K] @ B[b][K,N]; C = acc*scale[m] + bias[m]. Optional relu on B.
// 64x64 tile, BK=16, 256 threads, 4x4 per-thread micro-tile.
// ---------------------------------------------------------------------------
template <bool RELU_B>
__global__ __launch_bounds__(256)
void gemm_cbn(const float* __restrict__ A, const float* __restrict__ Bg,
              float* __restrict__ Cg, const float* __restrict__ scale,
              const float* __restrict__ bias, int M, int N, int K)
{
    const int b = blockIdx.z;
    const float* Bb = Bg + (size_t)b * K * N;
    float* Cb = Cg + (size_t)b * M * N;
    const int m0 = blockIdx.y * 64;
    const int n0 = blockIdx.x * 64;
    const int tid = threadIdx.x;

    __shared__ float As[16][64];
    __shared__ float Bs[16][64];

    float acc[4][4];
#pragma unroll
    for (int i = 0; i < 4; i++)
#pragma unroll
        for (int j = 0; j < 4; j++) acc[i][j] = 0.f;

    const int ty = tid >> 4, tx = tid & 15;
    const int ar = tid >> 2, ac = (tid & 3) * 4;
    const int br = tid >> 4, bc = (tid & 15) * 4;

    for (int k0 = 0; k0 < K; k0 += 16) {
        float4 a = *(const float4*)&A[(size_t)(m0 + ar) * K + k0 + ac];
        As[ac + 0][ar] = a.x; As[ac + 1][ar] = a.y;
        As[ac + 2][ar] = a.z; As[ac + 3][ar] = a.w;

        float4 v = *(const float4*)&Bb[(size_t)(k0 + br) * N + n0 + bc];
        if (RELU_B) {
            v.x = fmaxf(v.x, 0.f); v.y = fmaxf(v.y, 0.f);
            v.z = fmaxf(v.z, 0.f); v.w = fmaxf(v.w, 0.f);
        }
        *(float4*)&Bs[br][bc] = v;
        __syncthreads();

#pragma unroll
        for (int kk = 0; kk < 16; kk++) {
            float4 av = *(const float4*)&As[kk][ty * 4];
            float4 bv = *(const float4*)&Bs[kk][tx * 4];
            float aa[4] = {av.x, av.y, av.z, av.w};
            float bb[4] = {bv.x, bv.y, bv.z, bv.w};
#pragma unroll
            for (int i = 0; i < 4; i++)
#pragma unroll
                for (int j = 0; j < 4; j++)
                    acc[i][j] = fmaf(aa[i], bb[j], acc[i][j]);
        }
        __syncthreads();
    }

#pragma unroll
    for (int i = 0; i < 4; i++) {
        int m = m0 + ty * 4 + i;
        float s = scale[m], bi = bias[m];
        float4 o;
        o.x = fmaf(acc[i][0], s, bi);
        o.y = fmaf(acc[i][1], s, bi);
        o.z = fmaf(acc[i][2], s, bi);
        o.w = fmaf(acc[i][3], s, bi);
        *(float4*)&Cb[(size_t)m * N + n0 + tx * 4] = o;
    }
}

// ---------------------------------------------------------------------------
// Depthwise 3x3x3 conv on q channels (first 128 channels of g_qkv), pad=1,
// then scale/bias. One thread per (b,c,n).
// ---------------------------------------------------------------------------
__global__ __launch_bounds__(256)
void dwconv_kernel(const float* __restrict__ w,
                   const float* __restrict__ scale,
                   const float* __restrict__ bias)
{
    int idx = blockIdx.x * 256 + threadIdx.x;     // B*128*512 threads
    int n = idx & 511;
    int c = (idx >> 9) & 127;
    int b = idx >> 16;
    int xx = n & 7, yy = (n >> 3) & 7, zz = n >> 6;

    const float* src = g_qkv + ((size_t)b * HQKV + c) * N_;
    const float* wc = w + c * 27;
    float acc = 0.f;
#pragma unroll
    for (int dz = 0; dz < 3; dz++) {
        int z = zz + dz - 1;
        if (z < 0 || z > 7) continue;
#pragma unroll
        for (int dy = 0; dy < 3; dy++) {
            int y = yy + dy - 1;
            if (y < 0 || y > 7) continue;
#pragma unroll
            for (int dx = 0; dx < 3; dx++) {
                int x = xx + dx - 1;
                if (x < 0 || x > 7) continue;
                acc = fmaf(src[z * 64 + y * 8 + x], wc[dz * 9 + dy * 3 + dx], acc);
            }
        }
    }
    g_q[((size_t)b * NH_KD + c) * N_ + n] = fmaf(acc, scale[c], bias[c]);
}

// ---------------------------------------------------------------------------
// Fused attention per (b, h, 64-row n-tile):
//   S = qT k * 0.25 + attn_biases[h][bias_idxs]  (S kept in SMEM, 64x512)
//   softmax rows
//   out[d, n] = sum_m v[d,m] * P[n,m]            (64x64x512 reg-tiled GEMM)
// Dynamic SMEM: S 64*512 + kv 16*512 (reused for v tiles [m][d] stride 68)
//               + q 16*64 + bias row 512  = 42496 floats = 169984 B
// ---------------------------------------------------------------------------
__global__ __launch_bounds__(256)
void attn_kernel(const float* __restrict__ attn_biases,
                 const int* __restrict__ bias_idxs)
{
    extern __shared__ float sm[];
    float* S   = sm;               // [64][512]
    float* kvs = sm + 64 * 512;    // 8192 floats: k [16][512], later v [64m][68]
    float* qs  = kvs + 16 * 512;   // [16][64]
    float* ab  = qs + 16 * 64;     // [512]

    const int b  = blockIdx.z, h = blockIdx.y;
    const int n0 = blockIdx.x * 64;
    const int tid = threadIdx.x;

    const float* qb = g_q   + ((size_t)b * NH_KD + h * KDIM) * N_;
    const float* kb = g_qkv + ((size_t)b * HQKV + NH_KD + h * KDIM) * N_;
    const float* vb = g_qkv + ((size_t)b * HQKV + 2 * NH_KD + h * VDIM) * N_;

    // load q tile [16][64]
    {
        int r = tid >> 4, c = (tid & 15) * 4;
        *(float4*)&qs[r * 64 + c] = *(const float4*)&qb[(size_t)r * N_ + n0 + c];
    }
    // load k [16][512]
#pragma unroll
    for (int i = 0; i < 8; i++) {
        int e = tid + i * 256;              // float4 index, 2048 total
        int r = e >> 7, c = (e & 127) * 4;
        *(float4*)&kvs[r * 512 + c] = *(const float4*)&kb[(size_t)r * N_ + c];
    }
    if (tid < 128)
        *(float4*)&ab[tid * 4] = *(const float4*)&attn_biases[h * N_ + tid * 4];
    __syncthreads();

    // ---- QK^T: two passes over m-halves, 8n x 8m per thread ----
    const float sc = 0.25f;   // KEY_DIM^-0.5
#pragma unroll 1
    for (int mh = 0; mh < 2; mh++) {
        const int m  = mh * 256 + (tid & 31) * 8;
        const int nl = (tid >> 5) * 8;
        float acc[8][8];
#pragma unroll
        for (int i = 0; i < 8; i++)
#pragma unroll
            for (int j = 0; j < 8; j++) acc[i][j] = 0.f;

#pragma unroll
        for (int kc = 0; kc < 16; kc++) {
            float qv[8], kv[8];
            float4 t0 = *(const float4*)&qs[kc * 64 + nl];
            float4 t1 = *(const float4*)&qs[kc * 64 + nl + 4];
            qv[0] = t0.x; qv[1] = t0.y; qv[2] = t0.z; qv[3] = t0.w;
            qv[4] = t1.x; qv[5] = t1.y; qv[6] = t1.z; qv[7] = t1.w;
            float4 t2 = *(const float4*)&kvs[kc * 512 + m];
            float4 t3 = *(const float4*)&kvs[kc * 512 + m + 4];
            kv[0] = t2.x; kv[1] = t2.y; kv[2] = t2.z; kv[3] = t2.w;
            kv[4] = t3.x; kv[5] = t3.y; kv[6] = t3.z; kv[7] = t3.w;
#pragma unroll
            for (int i = 0; i < 8; i++)
#pragma unroll
                for (int j = 0; j < 8; j++)
                    acc[i][j] = fmaf(qv[i], kv[j], acc[i][j]);
        }
        // bias gather + store S
#pragma unroll
        for (int i = 0; i < 8; i++) {
            const int* idxr = bias_idxs + (size_t)(n0 + nl + i) * N_ + m;
#pragma unroll
            for (int j = 0; j < 8; j += 4) {
                int4 id = *(const int4*)&idxr[j];
                float4 o;
                o.x = fmaf(acc[i][j + 0], sc, ab[id.x]);
                o.y = fmaf(acc[i][j + 1], sc, ab[id.y]);
                o.z = fmaf(acc[i][j + 2], sc, ab[id.z]);
                o.w = fmaf(acc[i][j + 3], sc, ab[id.w]);
                *(float4*)&S[(nl + i) * 512 + m + j] = o;
            }
        }
    }
    __syncthreads();

    // ---- softmax: one warp per row, 8 rows per warp ----
    {
        const int warp = tid >> 5, lane = tid & 31;
        for (int r = warp; r < 64; r += 8) {
            float* row = S + r * 512;
            float e[16];
            float mx = -1e30f;
#pragma unroll
            for (int j = 0; j < 16; j++) { e[j] = row[lane + j * 32]; mx = fmaxf(mx, e[j]); }
#pragma unroll
            for (int off = 16; off; off >>= 1)
                mx = fmaxf(mx, __shfl_xor_sync(0xffffffffu, mx, off));
            float sum = 0.f;
#pragma unroll
            for (int j = 0; j < 16; j++) { e[j] = __expf(e[j] - mx); sum += e[j]; }
#pragma unroll
            for (int off = 16; off; off >>= 1)
                sum += __shfl_xor_sync(0xffffffffu, sum, off);
            float inv = 1.f / sum;
#pragma unroll
            for (int j = 0; j < 16; j++) row[lane + j * 32] = e[j] * inv;
        }
    }

    // ---- P·V: out tile [64 d][64 n], 4d x 4n per thread, v staged as
    //      v_s[m][d] (stride 68 -> conflict-free float4 loads) ----
    const int td = (tid & 15) * 4;     // lanes vary d -> p reads broadcast
    const int tn = (tid >> 4) * 4;
    float oacc[4][4];
#pragma unroll
    for (int i = 0; i < 4; i++)
#pragma unroll
        for (int j = 0; j < 4; j++) oacc[i][j] = 0.f;

#pragma unroll 1
    for (int mt = 0; mt < 8; mt++) {
        const int m0t = mt * 64;
        __syncthreads();   // previous tile's readers done (also fences k reuse)
#pragma unroll
        for (int i = 0; i < 4; i++) {
            int e = tid + i * 256;           // float4 idx, 1024 total
            int r = e >> 4, c = (e & 15) * 4;   // r = d row, c = m col
            float4 v = *(const float4*)&vb[(size_t)r * N_ + m0t + c];
            kvs[(c + 0) * 68 + r] = v.x;
            kvs[(c + 1) * 68 + r] = v.y;
            kvs[(c + 2) * 68 + r] = v.z;
            kvs[(c + 3) * 68 + r] = v.w;
        }
        __syncthreads();
#pragma unroll 2
        for (int mj = 0; mj < 64; mj += 4) {
            float vv[4][4], pp[4][4];
#pragma unroll
            for (int i = 0; i < 4; i++) {
                float4 t = *(const float4*)&kvs[(mj + i) * 68 + td];
                vv[i][0] = t.x; vv[i][1] = t.y; vv[i][2] = t.z; vv[i][3] = t.w;
            }
#pragma unroll
            for (int nn = 0; nn < 4; nn++) {
                float4 t = *(const float4*)&S[(tn + nn) * 512 + m0t + mj];
                pp[nn][0] = t.x; pp[nn][1] = t.y; pp[nn][2] = t.z; pp[nn][3] = t.w;
            }
#pragma unroll
            for (int nn = 0; nn < 4; nn++)
#pragma unroll
                for (int dd = 0; dd < 4; dd++)
#pragma unroll
                    for (int i = 0; i < 4; i++)
                        oacc[dd][nn] = fmaf(vv[i][dd], pp[nn][i], oacc[dd][nn]);
        }
    }

    float* ob = g_att + ((size_t)b * DH_ + h * VDIM) * N_;
#pragma unroll
    for (int dd = 0; dd < 4; dd++) {
        float4 o;
        o.x = oacc[dd][0]; o.y = oacc[dd][1]; o.z = oacc[dd][2]; o.w = oacc[dd][3];
        *(float4*)&ob[(size_t)(td + dd) * N_ + n0 + tn] = o;
    }
}

// ---------------------------------------------------------------------------
extern "C" void kernel_launch(void* const* d_in, const int* in_sizes, int n_in,
                              void* d_out, int out_size)
{
    const float* x          = (const float*)d_in[0];
    const float* qkv_w      = (const float*)d_in[1];
    const float* qkv_scale  = (const float*)d_in[2];
    const float* qkv_bias   = (const float*)d_in[3];
    const float* dw_w       = (const float*)d_in[4];
    const float* dw_scale   = (const float*)d_in[5];
    const float* dw_bias    = (const float*)d_in[6];
    const float* attn_bias  = (const float*)d_in[7];
    const float* proj_w     = (const float*)d_in[8];
    const float* proj_scale = (const float*)d_in[9];
    const float* proj_bias  = (const float*)d_in[10];
    const int*   bias_idxs  = (const int*)d_in[11];
    float* out = (float*)d_out;

    float *qkv_p, *att_p;
    cudaGetSymbolAddress((void**)&qkv_p, g_qkv);
    cudaGetSymbolAddress((void**)&att_p, g_att);

    const int attn_smem = 169984;
    cudaFuncSetAttribute(attn_kernel,
                         cudaFuncAttributeMaxDynamicSharedMemorySize, attn_smem);

    // 1) QKV pointwise conv + scale/bias:  [768,256] @ [256,512] per batch
    dim3 g1(N_ / 64, HQKV / 64, B_);
    gemm_cbn<false><<<g1, 256>>>(qkv_w, x, qkv_p, qkv_scale, qkv_bias,
                                 HQKV, N_, DIM_);

    // 2) depthwise 3x3x3 conv on q
    dwconv_kernel<<<(B_ * NH_KD * N_) / 256, 256>>>(dw_w, dw_scale, dw_bias);

    // 3) fused attention
    dim3 g2(N_ / 64, NHEADS, B_);
    attn_kernel<<<g2, 256, attn_smem>>>(attn_bias, bias_idxs);

    // 4) relu + proj:  [256,512] @ relu([512,512]) per batch
    dim3 g3(N_ / 64, DIM_ / 64, B_);
    gemm_cbn<true><<<g3, 256>>>(proj_w, att_p, out, proj_scale, proj_bias,
                                DIM_, N_, DH_);
}

// round 3
// speedup vs baseline: 1.1330x; 1.1330x over previous
#include <cuda_runtime.h>

#define B_      32
#define DIM_    256
#define N_      512
#define NHEADS  8
#define KDIM    16
#define NH_KD   128
#define DH_     512
#define HQKV    768
#define VDIM    64

typedef unsigned long long ull;

__device__ __forceinline__ ull dup2(float x) {
    ull r; asm("mov.b64 %0, {%1, %1};" : "=l"(r) : "f"(x)); return r;
}
__device__ __forceinline__ void ffma2(ull& d, ull a, ull b) {
    asm("fma.rn.f32x2 %0, %1, %2, %0;" : "+l"(d) : "l"(a), "l"(b));
}
__device__ __forceinline__ float2 unp(ull v) {
    float2 f; asm("mov.b64 {%0, %1}, %2;" : "=f"(f.x), "=f"(f.y) : "l"(v)); return f;
}

// Scratch (device globals: no allocation allowed)
__device__ float g_qkv[(size_t)B_ * HQKV * N_];   // [b][768][512]
__device__ float g_q  [(size_t)B_ * NH_KD * N_];  // dw-conv output
__device__ float g_att[(size_t)B_ * DH_ * N_];    // attention output (pre-relu)

// ---------------------------------------------------------------------------
// CBN GEMM: C[b] = A[M,K] @ B[b][K,N]; C = acc*scale[m]+bias[m]; opt. relu(B).
// 128x128 tile, BK=8, 256 threads, 8x8 micro-tile (two 4-wide halves),
// fp32x2 packed FMA (pairs along m).
// ---------------------------------------------------------------------------
template <bool RELU_B>
__global__ __launch_bounds__(256, 2)
void gemm_cbn(const float* __restrict__ A, const float* __restrict__ Bg,
              float* __restrict__ Cg, const float* __restrict__ scale,
              const float* __restrict__ bias, int M, int N, int K)
{
    const int b = blockIdx.z;
    const float* Bb = Bg + (size_t)b * K * N;
    float* Cb = Cg + (size_t)b * M * N;
    const int m0 = blockIdx.y * 128;
    const int n0 = blockIdx.x * 128;
    const int tid = threadIdx.x;

    __shared__ float As[8][128];
    __shared__ float Bs[8][128];

    const int ty = tid >> 4, tx = tid & 15;
    const int ar = tid >> 1, ac = (tid & 1) * 4;
    const int br = tid >> 5, bc = (tid & 31) * 4;

    // acc2[row-half][m-pair][n] ; lo lane = even m, hi lane = odd m
    ull acc2[2][2][8];
#pragma unroll
    for (int ih = 0; ih < 2; ih++)
#pragma unroll
        for (int i2 = 0; i2 < 2; i2++)
#pragma unroll
            for (int j = 0; j < 8; j++) acc2[ih][i2][j] = 0ULL;

    for (int k0 = 0; k0 < K; k0 += 8) {
        float4 a = *(const float4*)&A[(size_t)(m0 + ar) * K + k0 + ac];
        As[ac + 0][ar] = a.x; As[ac + 1][ar] = a.y;
        As[ac + 2][ar] = a.z; As[ac + 3][ar] = a.w;

        float4 v = *(const float4*)&Bb[(size_t)(k0 + br) * N + n0 + bc];
        if (RELU_B) {
            v.x = fmaxf(v.x, 0.f); v.y = fmaxf(v.y, 0.f);
            v.z = fmaxf(v.z, 0.f); v.w = fmaxf(v.w, 0.f);
        }
        *(float4*)&Bs[br][bc] = v;
        __syncthreads();

#pragma unroll
        for (int kk = 0; kk < 8; kk++) {
            ull a2[2][2];
            {
                ulonglong2 t0 = *(const ulonglong2*)&As[kk][ty * 4];
                a2[0][0] = t0.x; a2[0][1] = t0.y;
                ulonglong2 t1 = *(const ulonglong2*)&As[kk][64 + ty * 4];
                a2[1][0] = t1.x; a2[1][1] = t1.y;
            }
            float4 bl = *(const float4*)&Bs[kk][tx * 4];
            float4 bh = *(const float4*)&Bs[kk][64 + tx * 4];
            ull bd[8];
            bd[0] = dup2(bl.x); bd[1] = dup2(bl.y);
            bd[2] = dup2(bl.z); bd[3] = dup2(bl.w);
            bd[4] = dup2(bh.x); bd[5] = dup2(bh.y);
            bd[6] = dup2(bh.z); bd[7] = dup2(bh.w);
#pragma unroll
            for (int ih = 0; ih < 2; ih++)
#pragma unroll
                for (int i2 = 0; i2 < 2; i2++)
#pragma unroll
                    for (int j = 0; j < 8; j++)
                        ffma2(acc2[ih][i2][j], a2[ih][i2], bd[j]);
        }
        __syncthreads();
    }

    // epilogue: unpack, scale/bias, store
#pragma unroll
    for (int ih = 0; ih < 2; ih++) {
#pragma unroll
        for (int i2 = 0; i2 < 2; i2++) {
            const int mA = m0 + ih * 64 + ty * 4 + 2 * i2;
            float fl[8], fh[8];
#pragma unroll
            for (int j = 0; j < 8; j++) {
                float2 f = unp(acc2[ih][i2][j]);
                fl[j] = f.x; fh[j] = f.y;
            }
            float sL = scale[mA],     bL = bias[mA];
            float sH = scale[mA + 1], bH = bias[mA + 1];
            float4 o;
            o.x = fmaf(fl[0], sL, bL); o.y = fmaf(fl[1], sL, bL);
            o.z = fmaf(fl[2], sL, bL); o.w = fmaf(fl[3], sL, bL);
            *(float4*)&Cb[(size_t)mA * N + n0 + tx * 4] = o;
            o.x = fmaf(fl[4], sL, bL); o.y = fmaf(fl[5], sL, bL);
            o.z = fmaf(fl[6], sL, bL); o.w = fmaf(fl[7], sL, bL);
            *(float4*)&Cb[(size_t)mA * N + n0 + 64 + tx * 4] = o;
            o.x = fmaf(fh[0], sH, bH); o.y = fmaf(fh[1], sH, bH);
            o.z = fmaf(fh[2], sH, bH); o.w = fmaf(fh[3], sH, bH);
            *(float4*)&Cb[(size_t)(mA + 1) * N + n0 + tx * 4] = o;
            o.x = fmaf(fh[4], sH, bH); o.y = fmaf(fh[5], sH, bH);
            o.z = fmaf(fh[6], sH, bH); o.w = fmaf(fh[7], sH, bH);
            *(float4*)&Cb[(size_t)(mA + 1) * N + n0 + 64 + tx * 4] = o;
        }
    }
}

// ---------------------------------------------------------------------------
// Depthwise 3x3x3 conv on q channels, pad=1, then scale/bias.
// ---------------------------------------------------------------------------
__global__ __launch_bounds__(256)
void dwconv_kernel(const float* __restrict__ w,
                   const float* __restrict__ scale,
                   const float* __restrict__ bias)
{
    int idx = blockIdx.x * 256 + threadIdx.x;     // B*128*512 threads
    int n = idx & 511;
    int c = (idx >> 9) & 127;
    int b = idx >> 16;
    int xx = n & 7, yy = (n >> 3) & 7, zz = n >> 6;

    const float* src = g_qkv + ((size_t)b * HQKV + c) * N_;
    const float* wc = w + c * 27;
    float acc = 0.f;
#pragma unroll
    for (int dz = 0; dz < 3; dz++) {
        int z = zz + dz - 1;
        if (z < 0 || z > 7) continue;
#pragma unroll
        for (int dy = 0; dy < 3; dy++) {
            int y = yy + dy - 1;
            if (y < 0 || y > 7) continue;
#pragma unroll
            for (int dx = 0; dx < 3; dx++) {
                int x = xx + dx - 1;
                if (x < 0 || x > 7) continue;
                acc = fmaf(src[z * 64 + y * 8 + x], wc[dz * 9 + dy * 3 + dx], acc);
            }
        }
    }
    g_q[((size_t)b * NH_KD + c) * N_ + n] = fmaf(acc, scale[c], bias[c]);
}

// ---------------------------------------------------------------------------
// Fused attention per (b, h, 64-row n-tile). QK^T now uses fp32x2 FMA
// (pairs along m, packed k operand from SMEM, dup'd q).
// ---------------------------------------------------------------------------
__global__ __launch_bounds__(256)
void attn_kernel(const float* __restrict__ attn_biases,
                 const int* __restrict__ bias_idxs)
{
    extern __shared__ float sm[];
    float* S   = sm;               // [64][512]
    float* kvs = sm + 64 * 512;    // 8192 floats: k [16][512], later v [64m][68]
    float* qs  = kvs + 16 * 512;   // [16][64]
    float* ab  = qs + 16 * 64;     // [512]

    const int b  = blockIdx.z, h = blockIdx.y;
    const int n0 = blockIdx.x * 64;
    const int tid = threadIdx.x;

    const float* qb = g_q   + ((size_t)b * NH_KD + h * KDIM) * N_;
    const float* kb = g_qkv + ((size_t)b * HQKV + NH_KD + h * KDIM) * N_;
    const float* vb = g_qkv + ((size_t)b * HQKV + 2 * NH_KD + h * VDIM) * N_;

    // load q tile [16][64]
    {
        int r = tid >> 4, c = (tid & 15) * 4;
        *(float4*)&qs[r * 64 + c] = *(const float4*)&qb[(size_t)r * N_ + n0 + c];
    }
    // load k [16][512]
#pragma unroll
    for (int i = 0; i < 8; i++) {
        int e = tid + i * 256;              // float4 index, 2048 total
        int r = e >> 7, c = (e & 127) * 4;
        *(float4*)&kvs[r * 512 + c] = *(const float4*)&kb[(size_t)r * N_ + c];
    }
    if (tid < 128)
        *(float4*)&ab[tid * 4] = *(const float4*)&attn_biases[h * N_ + tid * 4];
    __syncthreads();

    // ---- QK^T: two passes over m-halves, 8n x 8m per thread, fp32x2 ----
    const float sc = 0.25f;   // KEY_DIM^-0.5
#pragma unroll 1
    for (int mh = 0; mh < 2; mh++) {
        const int m  = mh * 256 + (tid & 31) * 8;
        const int nl = (tid >> 5) * 8;
        ull acc2[8][4];     // [n][m-pair]; lo = even m, hi = odd m
#pragma unroll
        for (int i = 0; i < 8; i++)
#pragma unroll
            for (int j = 0; j < 4; j++) acc2[i][j] = 0ULL;

#pragma unroll
        for (int kc = 0; kc < 16; kc++) {
            float4 t0 = *(const float4*)&qs[kc * 64 + nl];
            float4 t1 = *(const float4*)&qs[kc * 64 + nl + 4];
            ull qd[8];
            qd[0] = dup2(t0.x); qd[1] = dup2(t0.y);
            qd[2] = dup2(t0.z); qd[3] = dup2(t0.w);
            qd[4] = dup2(t1.x); qd[5] = dup2(t1.y);
            qd[6] = dup2(t1.z); qd[7] = dup2(t1.w);
            ulonglong2 k0 = *(const ulonglong2*)&kvs[kc * 512 + m];
            ulonglong2 k1 = *(const ulonglong2*)&kvs[kc * 512 + m + 4];
            ull kv2[4] = {k0.x, k0.y, k1.x, k1.y};
#pragma unroll
            for (int i = 0; i < 8; i++)
#pragma unroll
                for (int j = 0; j < 4; j++)
                    ffma2(acc2[i][j], qd[i], kv2[j]);
        }
        // bias gather + store S
#pragma unroll
        for (int i = 0; i < 8; i++) {
            float f[8];
#pragma unroll
            for (int j2 = 0; j2 < 4; j2++) {
                float2 t = unp(acc2[i][j2]);
                f[2 * j2] = t.x; f[2 * j2 + 1] = t.y;
            }
            const int* idxr = bias_idxs + (size_t)(n0 + nl + i) * N_ + m;
#pragma unroll
            for (int j = 0; j < 8; j += 4) {
                int4 id = *(const int4*)&idxr[j];
                float4 o;
                o.x = fmaf(f[j + 0], sc, ab[id.x]);
                o.y = fmaf(f[j + 1], sc, ab[id.y]);
                o.z = fmaf(f[j + 2], sc, ab[id.z]);
                o.w = fmaf(f[j + 3], sc, ab[id.w]);
                *(float4*)&S[(nl + i) * 512 + m + j] = o;
            }
        }
    }
    __syncthreads();

    // ---- softmax: one warp per row, 8 rows per warp ----
    {
        const int warp = tid >> 5, lane = tid & 31;
        for (int r = warp; r < 64; r += 8) {
            float* row = S + r * 512;
            float e[16];
            float mx = -1e30f;
#pragma unroll
            for (int j = 0; j < 16; j++) { e[j] = row[lane + j * 32]; mx = fmaxf(mx, e[j]); }
#pragma unroll
            for (int off = 16; off; off >>= 1)
                mx = fmaxf(mx, __shfl_xor_sync(0xffffffffu, mx, off));
            float sum = 0.f;
#pragma unroll
            for (int j = 0; j < 16; j++) { e[j] = __expf(e[j] - mx); sum += e[j]; }
#pragma unroll
            for (int off = 16; off; off >>= 1)
                sum += __shfl_xor_sync(0xffffffffu, sum, off);
            float inv = 1.f / sum;
#pragma unroll
            for (int j = 0; j < 16; j++) row[lane + j * 32] = e[j] * inv;
        }
    }

    // ---- P·V: out tile [64 d][64 n], 4d x 4n per thread, v staged as
    //      v_s[m][d] (stride 68 -> conflict-free float4 loads) ----
    const int td = (tid & 15) * 4;     // lanes vary d -> p reads broadcast
    const int tn = (tid >> 4) * 4;
    float oacc[4][4];
#pragma unroll
    for (int i = 0; i < 4; i++)
#pragma unroll
        for (int j = 0; j < 4; j++) oacc[i][j] = 0.f;

#pragma unroll 1
    for (int mt = 0; mt < 8; mt++) {
        const int m0t = mt * 64;
        __syncthreads();   // previous tile's readers done (also fences k reuse)
#pragma unroll
        for (int i = 0; i < 4; i++) {
            int e = tid + i * 256;           // float4 idx, 1024 total
            int r = e >> 4, c = (e & 15) * 4;   // r = d row, c = m col
            float4 v = *(const float4*)&vb[(size_t)r * N_ + m0t + c];
            kvs[(c + 0) * 68 + r] = v.x;
            kvs[(c + 1) * 68 + r] = v.y;
            kvs[(c + 2) * 68 + r] = v.z;
            kvs[(c + 3) * 68 + r] = v.w;
        }
        __syncthreads();
#pragma unroll 2
        for (int mj = 0; mj < 64; mj += 4) {
            float vv[4][4], pp[4][4];
#pragma unroll
            for (int i = 0; i < 4; i++) {
                float4 t = *(const float4*)&kvs[(mj + i) * 68 + td];
                vv[i][0] = t.x; vv[i][1] = t.y; vv[i][2] = t.z; vv[i][3] = t.w;
            }
#pragma unroll
            for (int nn = 0; nn < 4; nn++) {
                float4 t = *(const float4*)&S[(tn + nn) * 512 + m0t + mj];
                pp[nn][0] = t.x; pp[nn][1] = t.y; pp[nn][2] = t.z; pp[nn][3] = t.w;
            }
#pragma unroll
            for (int nn = 0; nn < 4; nn++)
#pragma unroll
                for (int dd = 0; dd < 4; dd++)
#pragma unroll
                    for (int i = 0; i < 4; i++)
                        oacc[dd][nn] = fmaf(vv[i][dd], pp[nn][i], oacc[dd][nn]);
        }
    }

    float* ob = g_att + ((size_t)b * DH_ + h * VDIM) * N_;
#pragma unroll
    for (int dd = 0; dd < 4; dd++) {
        float4 o;
        o.x = oacc[dd][0]; o.y = oacc[dd][1]; o.z = oacc[dd][2]; o.w = oacc[dd][3];
        *(float4*)&ob[(size_t)(td + dd) * N_ + n0 + tn] = o;
    }
}

// ---------------------------------------------------------------------------
extern "C" void kernel_launch(void* const* d_in, const int* in_sizes, int n_in,
                              void* d_out, int out_size)
{
    const float* x          = (const float*)d_in[0];
    const float* qkv_w      = (const float*)d_in[1];
    const float* qkv_scale  = (const float*)d_in[2];
    const float* qkv_bias   = (const float*)d_in[3];
    const float* dw_w       = (const float*)d_in[4];
    const float* dw_scale   = (const float*)d_in[5];
    const float* dw_bias    = (const float*)d_in[6];
    const float* attn_bias  = (const float*)d_in[7];
    const float* proj_w     = (const float*)d_in[8];
    const float* proj_scale = (const float*)d_in[9];
    const float* proj_bias  = (const float*)d_in[10];
    const int*   bias_idxs  = (const int*)d_in[11];
    float* out = (float*)d_out;

    float *qkv_p, *att_p;
    cudaGetSymbolAddress((void**)&qkv_p, g_qkv);
    cudaGetSymbolAddress((void**)&att_p, g_att);

    const int attn_smem = 169984;
    cudaFuncSetAttribute(attn_kernel,
                         cudaFuncAttributeMaxDynamicSharedMemorySize, attn_smem);

    // 1) QKV pointwise conv + scale/bias:  [768,256] @ [256,512] per batch
    dim3 g1(N_ / 128, HQKV / 128, B_);
    gemm_cbn<false><<<g1, 256>>>(qkv_w, x, qkv_p, qkv_scale, qkv_bias,
                                 HQKV, N_, DIM_);

    // 2) depthwise 3x3x3 conv on q
    dwconv_kernel<<<(B_ * NH_KD * N_) / 256, 256>>>(dw_w, dw_scale, dw_bias);

    // 3) fused attention
    dim3 g2(N_ / 64, NHEADS, B_);
    attn_kernel<<<g2, 256, attn_smem>>>(attn_bias, bias_idxs);

    // 4) relu + proj:  [256,512] @ relu([512,512]) per batch
    dim3 g3(N_ / 128, DIM_ / 128, B_);
    gemm_cbn<true><<<g3, 256>>>(proj_w, att_p, out, proj_scale, proj_bias,
                                DIM_, N_, DH_);
}